// round 15
// baseline (speedup 1.0000x reference)
#include <cuda_runtime.h>

#define NTHR 512
#define TPG  16            // tokens per group
#define S    276           // staging row stride in floats (16*16 + 20 pad)

typedef unsigned long long ull;

// ---------------- shared memory layout (in floats) ----------------
#define WBT_SZ  (9*32*64)              // wbT[a][i][o], o contiguous
#define WOT_SZ  (9*32*32)              // woT[a][i][o]
#define XS_SZ   (32*S + 8)             // xs rows (aliased by gs in P3/P4)
#define HS_SZ   (64*S + 8)             // hs rows (aliased by out-staging)
#define WBT_OFF 0
#define WOT_OFF (WBT_OFF + WBT_SZ)
#define XS_OFF  (WOT_OFF + WOT_SZ)
#define HS_OFF  (XS_OFF + XS_SZ)
#define BB_OFF  (HS_OFF + HS_SZ)       // 64
#define BO_OFF  (BB_OFF + 64)          // 32
#define RW_OFF  (BO_OFF + 32)          // 16
#define F_TOTAL (RW_OFF + 16)
#define SMEM_BYTES (F_TOTAL * 4)

// component slot swizzle (bijective), bank-swizzled row offsets
__host__ __device__ constexpr int cslot(int k) { return k ^ (k >> 2); }
__host__ __device__ constexpr int rowX(int i)  { return XS_OFF + i * S + ((i >> 3) & 1) * 4; }
__host__ __device__ constexpr int rowH(int o)  { return HS_OFF + o * S + ((o >> 3) & 1) * 4; }

// ---------------- blade algebra ----------------
// blade order: 1,e0,e1,e2,e3,e01,e02,e03,e12,e13,e23,e012,e013,e023,e123,e0123
__constant__ int c_GRADE[16] = {0,1,1,1,1,2,2,2,2,2,2,3,3,3,3,4};
__constant__ int c_PART [16] = {-1,0,-1,-1,-1,2,3,4,-1,-1,-1,8,9,10,-1,14};
__constant__ int c_A2   [16] = {0,5,0,0,0,6,6,6,0,0,0,7,7,7,0,8};
// warp -> component; EK/NK interleaved in groups of 4 so each SMSP gets 2+2
__constant__ int c_KORD [16] = {1,5,6,7, 0,2,3,4, 11,12,13,15, 8,9,10,14};

// ---- compile-time Cayley tables ----
constexpr int MASKC[16]  = {0,1,2,4,8,3,5,9,6,10,12,7,11,13,14,15};
constexpr int IMASKC[16] = {0,1,2,5,3,6,8,11,4,7,9,12,10,13,14,15};
constexpr int popc4c(int x) { int v = 0; for (int b = 0; b < 4; b++) v += (x >> b) & 1; return v; }
constexpr int invcc(int A, int B) {
    int v = 0;
    for (int g = 0; g < 4; g++) if ((B >> g) & 1) v += popc4c(A >> (g + 1));
    return v;
}
struct CTerm { int i, j, s; };
struct CK    { CTerm t[16]; int n; };
struct CTabs { CK gp[16]; CK jc[16]; };
constexpr CTabs buildT() {
    CTabs T{};
    for (int i = 0; i < 16; i++)
        for (int j = 0; j < 16; j++) {
            int A = MASKC[i], B = MASKC[j];
            if (A & B & 1) continue;                    // e0*e0 = 0
            int s = (invcc(A, B) & 1) ? -1 : 1;
            int k = IMASKC[A ^ B];
            T.gp[k].t[T.gp[k].n].i = i;
            T.gp[k].t[T.gp[k].n].j = j;
            T.gp[k].t[T.gp[k].n].s = s;
            T.gp[k].n++;
        }
    int ds[16] = {};
    for (int i = 0; i < 16; i++) {
        int A = MASKC[i];
        ds[i] = (invcc(A, 15 ^ A) & 1) ? -1 : 1;
    }
    for (int i = 0; i < 16; i++)
        for (int j = 0; j < 16; j++) {
            int A = MASKC[i], B = MASKC[j];
            int da = 15 ^ A, db = 15 ^ B;
            if (da & db) continue;                      // wedge of duals vanishes
            int w  = (invcc(da, db) & 1) ? -1 : 1;
            int kk = IMASKC[A & B];
            int val = ds[i] * ds[j] * w * ds[kk];
            T.jc[kk].t[T.jc[kk].n].i = i;
            T.jc[kk].t[T.jc[kk].n].j = j;
            T.jc[kk].t[T.jc[kk].n].s = val;
            T.jc[kk].n++;
        }
    return T;
}
constexpr CTabs CT = buildT();

// ---- packed f32x2 helpers ----
__device__ __forceinline__ void fma2(ull& d, ull a, ull b) {
    asm("fma.rn.f32x2 %0, %1, %2, %0;" : "+l"(d) : "l"(a), "l"(b));
}
__device__ __forceinline__ ull pk2(float s) {
    ull d; asm("mov.b64 %0, {%1, %1};" : "=l"(d) : "f"(s)); return d;
}
__device__ __forceinline__ void add2(ull& d, ull a) {
    asm("add.rn.f32x2 %0, %0, %1;" : "+l"(d) : "l"(a));
}

// ---- P4 equi_linear (R9 version): component k, o-pair, token-half (8 tok) ----
__device__ __forceinline__ void el8(
    int k, int o0, int th, const float* __restrict__ wT,
    const float* __restrict__ smb, const float* __restrict__ bias,
    float* __restrict__ dsm)
{
    ull aA[4], aB[4];
    #pragma unroll
    for (int q = 0; q < 4; q++) { aA[q] = 0ull; aB[q] = 0ull; }

    int g  = c_GRADE[k];
    int sl = cslot(k) * 16 + th * 8;
    {
        const float* w = wT + (g * 32) * 32 + o0;
        #pragma unroll 8
        for (int i = 0; i < 32; i++) {
            float2 wv = *(const float2*)(w + i * 32);
            ull wa = pk2(wv.x), wb = pk2(wv.y);
            const float* xp = smb + rowX(i) + sl;
            ulonglong2 x0 = *(const ulonglong2*)(xp);
            ulonglong2 x1 = *(const ulonglong2*)(xp + 4);
            fma2(aA[0], x0.x, wa); fma2(aA[1], x0.y, wa);
            fma2(aA[2], x1.x, wa); fma2(aA[3], x1.y, wa);
            fma2(aB[0], x0.x, wb); fma2(aB[1], x0.y, wb);
            fma2(aB[2], x1.x, wb); fma2(aB[3], x1.y, wb);
        }
    }
    int pk = c_PART[k];
    if (pk >= 0) {
        int sl2 = cslot(pk) * 16 + th * 8;
        const float* w = wT + (c_A2[k] * 32) * 32 + o0;
        #pragma unroll 8
        for (int i = 0; i < 32; i++) {
            float2 wv = *(const float2*)(w + i * 32);
            ull wa = pk2(wv.x), wb = pk2(wv.y);
            const float* xp = smb + rowX(i) + sl2;
            ulonglong2 x0 = *(const ulonglong2*)(xp);
            ulonglong2 x1 = *(const ulonglong2*)(xp + 4);
            fma2(aA[0], x0.x, wa); fma2(aA[1], x0.y, wa);
            fma2(aA[2], x1.x, wa); fma2(aA[3], x1.y, wa);
            fma2(aB[0], x0.x, wb); fma2(aB[1], x0.y, wb);
            fma2(aB[2], x1.x, wb); fma2(aB[3], x1.y, wb);
        }
    }
    if (k == 0) {
        ull bA = pk2(bias[o0]), bB = pk2(bias[o0 + 1]);
        #pragma unroll
        for (int q = 0; q < 4; q++) { add2(aA[q], bA); add2(aB[q], bB); }
    }
    float* pA = dsm + rowH(o0) + sl;
    float* pB = dsm + rowH(o0 + 1) + sl;
    *(ulonglong2*)(pA)     = make_ulonglong2(aA[0], aA[1]);
    *(ulonglong2*)(pA + 4) = make_ulonglong2(aA[2], aA[3]);
    *(ulonglong2*)(pB)     = make_ulonglong2(aB[0], aB[1]);
    *(ulonglong2*)(pB + 4) = make_ulonglong2(aB[2], aB[3]);
}

// ---- P3: one component K, compile-time term list ----
template<int SIDE, int K>
__device__ __forceinline__ float bil_k(const float (&L)[16], const float (&R)[16]) {
    constexpr CK ck = SIDE ? CT.jc[K] : CT.gp[K];
    float acc = 0.f;
    #pragma unroll
    for (int e = 0; e < ck.n; e++) {
        float l = (ck.t[e].s < 0) ? -L[ck.t[e].i] : L[ck.t[e].i];
        acc = fmaf(l, R[ck.t[e].j], acc);
    }
    return acc;
}

template<int SIDE, int K>
__device__ __forceinline__ void bil_all(const float (&L)[16], const float (&R)[16],
                                        float* __restrict__ dst, float scale) {
    if constexpr (K < 16) {
        float v = bil_k<SIDE, K>(L, R);
        if constexpr (SIDE) v *= scale;
        dst[cslot(K) * 16] = v;
        bil_all<SIDE, K + 1>(L, R, dst, scale);
    }
}

__global__ __launch_bounds__(NTHR, 1)
void gatr_fused_kernel(
    const float* __restrict__ x, const float* __restrict__ ref,
    const float* __restrict__ w_bil, const float* __restrict__ b_bil,
    const float* __restrict__ w_out, const float* __restrict__ b_out,
    float* __restrict__ out, int ngroups)
{
    extern __shared__ float sm[];
    float* wbT = sm + WBT_OFF;
    float* woT = sm + WOT_OFF;
    float* bb  = sm + BB_OFF;
    float* bo  = sm + BO_OFF;
    float* rw  = sm + RW_OFF;

    const int tid = threadIdx.x;

    // ---- stage weights transposed ----
    for (int e = tid; e < 64 * 32 * 9; e += NTHR) {
        int o = e / 288, r = e % 288, i = r / 9, a = r % 9;
        wbT[(a * 32 + i) * 64 + o] = w_bil[e];
    }
    for (int e = tid; e < 32 * 32 * 9; e += NTHR) {
        int o = e / 288, r = e % 288, i = r / 9, a = r % 9;
        woT[(a * 32 + i) * 32 + o] = w_out[e];
    }
    if (tid < 64) bb[tid] = b_bil[tid];
    if (tid < 32) bo[tid] = b_out[tid];
    __syncthreads();   // wbT ready for register capture

    const int w_id = tid >> 5, lane = tid & 31;
    const int k_my = c_KORD[w_id];
    const int pk_my = c_PART[k_my];
    const int sl_my = cslot(k_my) * 16;

    // ---- persistent P2 table-1 weights in registers (one o-pair per lane) ----
    float2 wr[32];
    {
        const float* w = wbT + (c_GRADE[k_my] * 32) * 64 + 2 * lane;
        #pragma unroll
        for (int i = 0; i < 32; i++) wr[i] = *(const float2*)(w + i * 64);
    }

    const int e_id = tid & 127;
    const int t0   = (tid >> 7) * 4;

    // ---- prefetch + stage first group ----
    float4 pf[4];
    float  prw = 0.f;
    {
        int g = blockIdx.x;
        size_t base = ((size_t)g * TPG + t0) * 512 + (size_t)e_id * 4;
        #pragma unroll
        for (int j = 0; j < 4; j++) pf[j] = *(const float4*)(x + base + (size_t)j * 512);
        if (tid < TPG) prw = ref[((size_t)g * TPG + tid) * 16 + 15];

        const float* p0 = (const float*)&pf[0];
        const float* p1 = (const float*)&pf[1];
        const float* p2 = (const float*)&pf[2];
        const float* p3 = (const float*)&pf[3];
        #pragma unroll
        for (int c = 0; c < 4; c++) {
            int k = (e_id & 3) * 4 + c;
            float* d = sm + rowX(e_id >> 2) + cslot(k) * 16 + t0;
            *(float4*)d = make_float4(p0[c], p1[c], p2[c], p3[c]);
        }
        if (tid < TPG) rw[tid] = prw;
    }

    for (int g = blockIdx.x; g < ngroups; g += gridDim.x) {
        __syncthreads();   // xs / rw ready

        // ---- P2: equi_linear #1 -> hs rows 0..63 (warp = component, o-pair) ----
        // table-1 weights from registers; EK table-2 streamed from LDS
        {
            const int o0 = 2 * lane;
            ull aA[8], aB[8];
            #pragma unroll
            for (int q = 0; q < 8; q++) { aA[q] = 0ull; aB[q] = 0ull; }

            #pragma unroll
            for (int i = 0; i < 32; i++) {
                ull wa = pk2(wr[i].x), wb = pk2(wr[i].y);
                const float* xp = sm + rowX(i) + sl_my;
                ulonglong2 x0 = *(const ulonglong2*)(xp);
                ulonglong2 x1 = *(const ulonglong2*)(xp + 4);
                ulonglong2 x2 = *(const ulonglong2*)(xp + 8);
                ulonglong2 x3 = *(const ulonglong2*)(xp + 12);
                fma2(aA[0], x0.x, wa); fma2(aA[1], x0.y, wa);
                fma2(aA[2], x1.x, wa); fma2(aA[3], x1.y, wa);
                fma2(aA[4], x2.x, wa); fma2(aA[5], x2.y, wa);
                fma2(aA[6], x3.x, wa); fma2(aA[7], x3.y, wa);
                fma2(aB[0], x0.x, wb); fma2(aB[1], x0.y, wb);
                fma2(aB[2], x1.x, wb); fma2(aB[3], x1.y, wb);
                fma2(aB[4], x2.x, wb); fma2(aB[5], x2.y, wb);
                fma2(aB[6], x3.x, wb); fma2(aB[7], x3.y, wb);
            }
            if (pk_my >= 0) {
                const int sl2 = cslot(pk_my) * 16;
                const float* w = wbT + (c_A2[k_my] * 32) * 64 + o0;
                #pragma unroll 8
                for (int i = 0; i < 32; i++) {
                    float2 wv = *(const float2*)(w + i * 64);
                    ull wa = pk2(wv.x), wb = pk2(wv.y);
                    const float* xp = sm + rowX(i) + sl2;
                    ulonglong2 x0 = *(const ulonglong2*)(xp);
                    ulonglong2 x1 = *(const ulonglong2*)(xp + 4);
                    ulonglong2 x2 = *(const ulonglong2*)(xp + 8);
                    ulonglong2 x3 = *(const ulonglong2*)(xp + 12);
                    fma2(aA[0], x0.x, wa); fma2(aA[1], x0.y, wa);
                    fma2(aA[2], x1.x, wa); fma2(aA[3], x1.y, wa);
                    fma2(aA[4], x2.x, wa); fma2(aA[5], x2.y, wa);
                    fma2(aA[6], x3.x, wa); fma2(aA[7], x3.y, wa);
                    fma2(aB[0], x0.x, wb); fma2(aB[1], x0.y, wb);
                    fma2(aB[2], x1.x, wb); fma2(aB[3], x1.y, wb);
                    fma2(aB[4], x2.x, wb); fma2(aB[5], x2.y, wb);
                    fma2(aB[6], x3.x, wb); fma2(aB[7], x3.y, wb);
                }
            }
            if (k_my == 0) {
                ull bA = pk2(bb[o0]), bB = pk2(bb[o0 + 1]);
                #pragma unroll
                for (int q = 0; q < 8; q++) { add2(aA[q], bA); add2(aB[q], bB); }
            }
            float* pA = sm + rowH(o0) + sl_my;
            float* pB = sm + rowH(o0 + 1) + sl_my;
            *(ulonglong2*)(pA)      = make_ulonglong2(aA[0], aA[1]);
            *(ulonglong2*)(pA + 4)  = make_ulonglong2(aA[2], aA[3]);
            *(ulonglong2*)(pA + 8)  = make_ulonglong2(aA[4], aA[5]);
            *(ulonglong2*)(pA + 12) = make_ulonglong2(aA[6], aA[7]);
            *(ulonglong2*)(pB)      = make_ulonglong2(aB[0], aB[1]);
            *(ulonglong2*)(pB + 4)  = make_ulonglong2(aB[2], aB[3]);
            *(ulonglong2*)(pB + 8)  = make_ulonglong2(aB[4], aB[5]);
            *(ulonglong2*)(pB + 12) = make_ulonglong2(aB[6], aB[7]);
        }
        __syncthreads();

        // ---- P3: GP + join -> gs (xs region) rows 0..31 (512 threads) ----
        {
            int side = tid >> 8, c = (tid >> 4) & 15, t = tid & 15;
            const float* Lp = sm + rowH(side * 32 + c) + t;
            const float* Rp = sm + rowH(side * 32 + 16 + c) + t;
            float L[16], R[16];
            #pragma unroll
            for (int i = 0; i < 16; i++) {
                L[i] = Lp[cslot(i) * 16];
                R[i] = Rp[cslot(i) * 16];
            }
            float* dst = sm + rowX(side * 16 + c) + t;
            float scale = rw[t];
            if (side == 0) bil_all<0, 0>(L, R, dst, scale);
            else           bil_all<1, 0>(L, R, dst, scale);
        }
        __syncthreads();

        // prefetch next group here (lower reg pressure than during P2;
        // still a full P4 phase of latency cover before use in P5)
        int gn = g + gridDim.x;
        bool more = gn < ngroups;
        if (more) {
            size_t base = ((size_t)gn * TPG + t0) * 512 + (size_t)e_id * 4;
            #pragma unroll
            for (int j = 0; j < 4; j++) pf[j] = *(const float4*)(x + base + (size_t)j * 512);
            if (tid < TPG) prw = ref[((size_t)gn * TPG + tid) * 16 + 15];
        }

        // ---- P4: equi_linear #2 -> staging in hs rows 0..31 ----
        {
            int op = lane >> 1, th = lane & 1;
            el8(k_my, 2 * op, th, woT, sm, bo, sm);
        }
        __syncthreads();

        // ---- P5: coalesced store + stage next group's x ----
        {
            float4 sv[4];
            #pragma unroll
            for (int c = 0; c < 4; c++) {
                int k = (e_id & 3) * 4 + c;
                sv[c] = *(const float4*)(sm + rowH(e_id >> 2) + cslot(k) * 16 + t0);
            }
            size_t base = ((size_t)g * TPG + t0) * 512 + (size_t)e_id * 4;
            const float* s0 = (const float*)&sv[0];
            const float* s1 = (const float*)&sv[1];
            const float* s2 = (const float*)&sv[2];
            const float* s3 = (const float*)&sv[3];
            #pragma unroll
            for (int j = 0; j < 4; j++)
                *(float4*)(out + base + (size_t)j * 512) =
                    make_float4(s0[j], s1[j], s2[j], s3[j]);

            if (more) {
                const float* p0 = (const float*)&pf[0];
                const float* p1 = (const float*)&pf[1];
                const float* p2 = (const float*)&pf[2];
                const float* p3 = (const float*)&pf[3];
                #pragma unroll
                for (int c = 0; c < 4; c++) {
                    int k = (e_id & 3) * 4 + c;
                    float* d = sm + rowX(e_id >> 2) + cslot(k) * 16 + t0;
                    *(float4*)d = make_float4(p0[c], p1[c], p2[c], p3[c]);
                }
                if (tid < TPG) rw[tid] = prw;
            }
        }
    }
}

extern "C" void kernel_launch(void* const* d_in, const int* in_sizes, int n_in,
                              void* d_out, int out_size)
{
    const float* x     = (const float*)d_in[0];
    const float* ref   = (const float*)d_in[1];
    const float* w_bil = (const float*)d_in[2];
    const float* b_bil = (const float*)d_in[3];
    const float* w_out = (const float*)d_in[4];
    const float* b_out = (const float*)d_in[5];
    float* out = (float*)d_out;

    int ntok    = in_sizes[0] / 512;   // 32 channels * 16 components
    int ngroups = ntok / TPG;

    cudaFuncSetAttribute(gatr_fused_kernel,
                         cudaFuncAttributeMaxDynamicSharedMemorySize, SMEM_BYTES);
    gatr_fused_kernel<<<152, NTHR, SMEM_BYTES>>>(x, ref, w_bil, b_bil, w_out, b_out,
                                                 out, ngroups);
}

// round 16
// speedup vs baseline: 1.2787x; 1.2787x over previous
#include <cuda_runtime.h>

#define NTHR 512
#define TPG  16            // tokens per group
#define S    276           // staging row stride in floats

typedef unsigned long long ull;
typedef unsigned int uint;

// ---------------- shared memory layout (in floats) ----------------
// weights for mma: [a][o][i] with i padded to 36 (conflict-free A-frag loads)
#define WB2_SZ  (9*64*36)              // 20736
#define WO2_SZ  (9*32*36)              // 10368
#define XS_SZ   (32*S + 8)             // xs rows (aliased by gs in P3/P4)
#define HS_SZ   (64*S + 8)             // hs rows
#define WB2_OFF 0
#define WO2_OFF (WB2_OFF + WB2_SZ)
#define XS_OFF  (WO2_OFF + WO2_SZ)
#define HS_OFF  (XS_OFF + XS_SZ)
#define BB_OFF  (HS_OFF + HS_SZ)       // 64
#define BO_OFF  (BB_OFF + 64)          // 32
#define RW_OFF  (BO_OFF + 32)          // 16
#define F_TOTAL (RW_OFF + 16)
#define SMEM_BYTES (F_TOTAL * 4)       // 230912 <= 232448

// component slot swizzle (bijective), bank-swizzled row offsets
__host__ __device__ constexpr int cslot(int k) { return k ^ (k >> 2); }
__host__ __device__ constexpr int rowX(int i)  { return XS_OFF + i * S + ((i >> 3) & 1) * 4; }
__host__ __device__ constexpr int rowH(int o)  { return HS_OFF + o * S + ((o >> 3) & 1) * 4; }

// ---------------- blade algebra ----------------
// blade order: 1,e0,e1,e2,e3,e01,e02,e03,e12,e13,e23,e012,e013,e023,e123,e0123
__constant__ int c_GRADE[16] = {0,1,1,1,1,2,2,2,2,2,2,3,3,3,3,4};
__constant__ int c_PART [16] = {-1,0,-1,-1,-1,2,3,4,-1,-1,-1,8,9,10,-1,14};
__constant__ int c_A2   [16] = {0,5,0,0,0,6,6,6,0,0,0,7,7,7,0,8};
__constant__ int c_KORD [16] = {1,5,6,7, 0,2,3,4, 11,12,13,15, 8,9,10,14};

// ---- compile-time Cayley tables (unchanged) ----
constexpr int MASKC[16]  = {0,1,2,4,8,3,5,9,6,10,12,7,11,13,14,15};
constexpr int IMASKC[16] = {0,1,2,5,3,6,8,11,4,7,9,12,10,13,14,15};
constexpr int popc4c(int x) { int v = 0; for (int b = 0; b < 4; b++) v += (x >> b) & 1; return v; }
constexpr int invcc(int A, int B) {
    int v = 0;
    for (int g = 0; g < 4; g++) if ((B >> g) & 1) v += popc4c(A >> (g + 1));
    return v;
}
struct CTerm { int i, j, s; };
struct CK    { CTerm t[16]; int n; };
struct CTabs { CK gp[16]; CK jc[16]; };
constexpr CTabs buildT() {
    CTabs T{};
    for (int i = 0; i < 16; i++)
        for (int j = 0; j < 16; j++) {
            int A = MASKC[i], B = MASKC[j];
            if (A & B & 1) continue;
            int s = (invcc(A, B) & 1) ? -1 : 1;
            int k = IMASKC[A ^ B];
            T.gp[k].t[T.gp[k].n].i = i;
            T.gp[k].t[T.gp[k].n].j = j;
            T.gp[k].t[T.gp[k].n].s = s;
            T.gp[k].n++;
        }
    int ds[16] = {};
    for (int i = 0; i < 16; i++) {
        int A = MASKC[i];
        ds[i] = (invcc(A, 15 ^ A) & 1) ? -1 : 1;
    }
    for (int i = 0; i < 16; i++)
        for (int j = 0; j < 16; j++) {
            int A = MASKC[i], B = MASKC[j];
            int da = 15 ^ A, db = 15 ^ B;
            if (da & db) continue;
            int w  = (invcc(da, db) & 1) ? -1 : 1;
            int kk = IMASKC[A & B];
            int val = ds[i] * ds[j] * w * ds[kk];
            T.jc[kk].t[T.jc[kk].n].i = i;
            T.jc[kk].t[T.jc[kk].n].j = j;
            T.jc[kk].t[T.jc[kk].n].s = val;
            T.jc[kk].n++;
        }
    return T;
}
constexpr CTabs CT = buildT();

// ---- tf32 helpers ----
__device__ __forceinline__ uint tf32c(float x) {
    uint r; asm("cvt.rna.tf32.f32 %0, %1;" : "=r"(r) : "f"(x)); return r;
}
__device__ __forceinline__ void split2(float x, uint& hi, uint& lo) {
    hi = tf32c(x);
    lo = tf32c(x - __uint_as_float(hi));
}
__device__ __forceinline__ void mma8(float (&c)[4],
                                     uint a0, uint a1, uint a2, uint a3,
                                     uint b0, uint b1) {
    asm volatile(
        "mma.sync.aligned.m16n8k8.row.col.f32.tf32.tf32.f32 "
        "{%0,%1,%2,%3}, {%4,%5,%6,%7}, {%8,%9}, {%0,%1,%2,%3};"
        : "+f"(c[0]), "+f"(c[1]), "+f"(c[2]), "+f"(c[3])
        : "r"(a0), "r"(a1), "r"(a2), "r"(a3), "r"(b0), "r"(b1));
}

// ---- one K=32 GEMM pass: C[MT][2][4] += W[MT*16 x 32] * X[32 x 16], 3xTF32 ----
// Wt: [o][i] rows of 36; B from staged rows rowX(i), slot base `slot`.
template<int MT>
__device__ __forceinline__ void mma_pass(
    float (&C)[MT][2][4], const float* __restrict__ Wt,
    const float* __restrict__ smb, int slot, int gr, int gc)
{
    #pragma unroll
    for (int s = 0; s < 4; s++) {
        // B fragments (k = s*8 + {gc, gc+4}, n = nt*8 + gr)
        uint bh[2][2], bl[2][2];
        #pragma unroll
        for (int nt = 0; nt < 2; nt++) {
            float f0 = smb[rowX(s * 8 + gc)     + slot + nt * 8 + gr];
            float f1 = smb[rowX(s * 8 + gc + 4) + slot + nt * 8 + gr];
            split2(f0, bh[nt][0], bl[nt][0]);
            split2(f1, bh[nt][1], bl[nt][1]);
        }
        #pragma unroll
        for (int mt = 0; mt < MT; mt++) {
            const float* wb = Wt + (mt * 16 + gr) * 36 + s * 8 + gc;
            float a0f = wb[0];
            float a1f = wb[8 * 36];
            float a2f = wb[4];
            float a3f = wb[8 * 36 + 4];
            uint ah0, al0, ah1, al1, ah2, al2, ah3, al3;
            split2(a0f, ah0, al0); split2(a1f, ah1, al1);
            split2(a2f, ah2, al2); split2(a3f, ah3, al3);
            #pragma unroll
            for (int nt = 0; nt < 2; nt++) {
                mma8(C[mt][nt], ah0, ah1, ah2, ah3, bh[nt][0], bh[nt][1]);
                mma8(C[mt][nt], ah0, ah1, ah2, ah3, bl[nt][0], bl[nt][1]);
                mma8(C[mt][nt], al0, al1, al2, al3, bh[nt][0], bh[nt][1]);
            }
        }
    }
}

// ---- P3: one component K, compile-time term list ----
template<int SIDE, int K>
__device__ __forceinline__ float bil_k(const float (&L)[16], const float (&R)[16]) {
    constexpr CK ck = SIDE ? CT.jc[K] : CT.gp[K];
    float acc = 0.f;
    #pragma unroll
    for (int e = 0; e < ck.n; e++) {
        float l = (ck.t[e].s < 0) ? -L[ck.t[e].i] : L[ck.t[e].i];
        acc = fmaf(l, R[ck.t[e].j], acc);
    }
    return acc;
}
template<int SIDE, int K>
__device__ __forceinline__ void bil_all(const float (&L)[16], const float (&R)[16],
                                        float* __restrict__ dst, float scale) {
    if constexpr (K < 16) {
        float v = bil_k<SIDE, K>(L, R);
        if constexpr (SIDE) v *= scale;
        dst[cslot(K) * 16] = v;
        bil_all<SIDE, K + 1>(L, R, dst, scale);
    }
}

__global__ __launch_bounds__(NTHR, 1)
void gatr_fused_kernel(
    const float* __restrict__ x, const float* __restrict__ ref,
    const float* __restrict__ w_bil, const float* __restrict__ b_bil,
    const float* __restrict__ w_out, const float* __restrict__ b_out,
    float* __restrict__ out, int ngroups)
{
    extern __shared__ float sm[];
    float* wbA = sm + WB2_OFF;   // [a][o][36]
    float* woA = sm + WO2_OFF;   // [a][o][36]
    float* bb  = sm + BB_OFF;
    float* bo  = sm + BO_OFF;
    float* rw  = sm + RW_OFF;

    const int tid = threadIdx.x;

    // ---- stage weights as [a][o][i+pad] ----
    for (int e = tid; e < 64 * 32 * 9; e += NTHR) {
        int o = e / 288, r = e % 288, i = r / 9, a = r % 9;
        wbA[(a * 64 + o) * 36 + i] = w_bil[e];
    }
    for (int e = tid; e < 32 * 32 * 9; e += NTHR) {
        int o = e / 288, r = e % 288, i = r / 9, a = r % 9;
        woA[(a * 32 + o) * 36 + i] = w_out[e];
    }
    if (tid < 64) bb[tid] = b_bil[tid];
    if (tid < 32) bo[tid] = b_out[tid];

    const int e_id = tid & 127;
    const int t0   = (tid >> 7) * 4;

    // ---- prefetch + stage first group ----
    float4 pf[4];
    float  prw = 0.f;
    {
        int g = blockIdx.x;
        size_t base = ((size_t)g * TPG + t0) * 512 + (size_t)e_id * 4;
        #pragma unroll
        for (int j = 0; j < 4; j++) pf[j] = *(const float4*)(x + base + (size_t)j * 512);
        if (tid < TPG) prw = ref[((size_t)g * TPG + tid) * 16 + 15];

        const float* p0 = (const float*)&pf[0];
        const float* p1 = (const float*)&pf[1];
        const float* p2 = (const float*)&pf[2];
        const float* p3 = (const float*)&pf[3];
        #pragma unroll
        for (int c = 0; c < 4; c++) {
            int k = (e_id & 3) * 4 + c;
            float* d = sm + rowX(e_id >> 2) + cslot(k) * 16 + t0;
            *(float4*)d = make_float4(p0[c], p1[c], p2[c], p3[c]);
        }
        if (tid < TPG) rw[tid] = prw;
    }

    const int w_id = tid >> 5, lane = tid & 31;
    const int gr = lane >> 2, gc = lane & 3;
    const int k_my  = c_KORD[w_id];
    const int pk_my = c_PART[k_my];
    const int sl_my = cslot(k_my) * 16;

    for (int g = blockIdx.x; g < ngroups; g += gridDim.x) {
        __syncthreads();   // xs / rw ready (also weights on first iter)

        // ---- P2: equi_linear #1 via tensor cores -> hs rows 0..63 ----
        {
            float C[4][2][4];
            #pragma unroll
            for (int mt = 0; mt < 4; mt++)
                #pragma unroll
                for (int nt = 0; nt < 2; nt++)
                    #pragma unroll
                    for (int j = 0; j < 4; j++) C[mt][nt][j] = 0.f;

            mma_pass<4>(C, wbA + (c_GRADE[k_my] * 64) * 36, sm, sl_my, gr, gc);
            if (pk_my >= 0)
                mma_pass<4>(C, wbA + (c_A2[k_my] * 64) * 36, sm,
                            cslot(pk_my) * 16, gr, gc);

            if (k_my == 0) {
                #pragma unroll
                for (int mt = 0; mt < 4; mt++) {
                    float bA = bb[mt * 16 + gr];
                    float bB = bb[mt * 16 + gr + 8];
                    #pragma unroll
                    for (int nt = 0; nt < 2; nt++) {
                        C[mt][nt][0] += bA; C[mt][nt][1] += bA;
                        C[mt][nt][2] += bB; C[mt][nt][3] += bB;
                    }
                }
            }
            #pragma unroll
            for (int mt = 0; mt < 4; mt++) {
                int o = mt * 16 + gr;
                #pragma unroll
                for (int nt = 0; nt < 2; nt++) {
                    int col = sl_my + nt * 8 + 2 * gc;
                    *(float2*)(sm + rowH(o) + col)     = make_float2(C[mt][nt][0], C[mt][nt][1]);
                    *(float2*)(sm + rowH(o + 8) + col) = make_float2(C[mt][nt][2], C[mt][nt][3]);
                }
            }
        }
        __syncthreads();

        // ---- P3: GP + join -> gs (xs region) rows 0..31 (512 threads) ----
        {
            int side = tid >> 8, c = (tid >> 4) & 15, t = tid & 15;
            const float* Lp = sm + rowH(side * 32 + c) + t;
            const float* Rp = sm + rowH(side * 32 + 16 + c) + t;
            float L[16], R[16];
            #pragma unroll
            for (int i = 0; i < 16; i++) {
                L[i] = Lp[cslot(i) * 16];
                R[i] = Rp[cslot(i) * 16];
            }
            float* dst = sm + rowX(side * 16 + c) + t;
            float scale = rw[t];
            if (side == 0) bil_all<0, 0>(L, R, dst, scale);
            else           bil_all<1, 0>(L, R, dst, scale);
        }
        __syncthreads();

        // prefetch next group (latency covered by P4)
        int gn = g + gridDim.x;
        bool more = gn < ngroups;
        if (more) {
            size_t base = ((size_t)gn * TPG + t0) * 512 + (size_t)e_id * 4;
            #pragma unroll
            for (int j = 0; j < 4; j++) pf[j] = *(const float4*)(x + base + (size_t)j * 512);
            if (tid < TPG) prw = ref[((size_t)gn * TPG + tid) * 16 + 15];
        }

        // ---- P4: equi_linear #2 via tensor cores -> hs rows 0..31 ----
        {
            float C[2][2][4];
            #pragma unroll
            for (int mt = 0; mt < 2; mt++)
                #pragma unroll
                for (int nt = 0; nt < 2; nt++)
                    #pragma unroll
                    for (int j = 0; j < 4; j++) C[mt][nt][j] = 0.f;

            mma_pass<2>(C, woA + (c_GRADE[k_my] * 32) * 36, sm, sl_my, gr, gc);
            if (pk_my >= 0)
                mma_pass<2>(C, woA + (c_A2[k_my] * 32) * 36, sm,
                            cslot(pk_my) * 16, gr, gc);

            if (k_my == 0) {
                #pragma unroll
                for (int mt = 0; mt < 2; mt++) {
                    float bA = bo[mt * 16 + gr];
                    float bB = bo[mt * 16 + gr + 8];
                    #pragma unroll
                    for (int nt = 0; nt < 2; nt++) {
                        C[mt][nt][0] += bA; C[mt][nt][1] += bA;
                        C[mt][nt][2] += bB; C[mt][nt][3] += bB;
                    }
                }
            }
            #pragma unroll
            for (int mt = 0; mt < 2; mt++) {
                int o = mt * 16 + gr;
                #pragma unroll
                for (int nt = 0; nt < 2; nt++) {
                    int col = sl_my + nt * 8 + 2 * gc;
                    *(float2*)(sm + rowH(o) + col)     = make_float2(C[mt][nt][0], C[mt][nt][1]);
                    *(float2*)(sm + rowH(o + 8) + col) = make_float2(C[mt][nt][2], C[mt][nt][3]);
                }
            }
        }
        __syncthreads();

        // ---- P5: coalesced store + stage next group's x ----
        {
            float4 sv[4];
            #pragma unroll
            for (int c = 0; c < 4; c++) {
                int k = (e_id & 3) * 4 + c;
                sv[c] = *(const float4*)(sm + rowH(e_id >> 2) + cslot(k) * 16 + t0);
            }
            size_t base = ((size_t)g * TPG + t0) * 512 + (size_t)e_id * 4;
            const float* s0 = (const float*)&sv[0];
            const float* s1 = (const float*)&sv[1];
            const float* s2 = (const float*)&sv[2];
            const float* s3 = (const float*)&sv[3];
            #pragma unroll
            for (int j = 0; j < 4; j++)
                *(float4*)(out + base + (size_t)j * 512) =
                    make_float4(s0[j], s1[j], s2[j], s3[j]);

            if (more) {
                const float* p0 = (const float*)&pf[0];
                const float* p1 = (const float*)&pf[1];
                const float* p2 = (const float*)&pf[2];
                const float* p3 = (const float*)&pf[3];
                #pragma unroll
                for (int c = 0; c < 4; c++) {
                    int k = (e_id & 3) * 4 + c;
                    float* d = sm + rowX(e_id >> 2) + cslot(k) * 16 + t0;
                    *(float4*)d = make_float4(p0[c], p1[c], p2[c], p3[c]);
                }
                if (tid < TPG) rw[tid] = prw;
            }
        }
    }
}

extern "C" void kernel_launch(void* const* d_in, const int* in_sizes, int n_in,
                              void* d_out, int out_size)
{
    const float* x     = (const float*)d_in[0];
    const float* ref   = (const float*)d_in[1];
    const float* w_bil = (const float*)d_in[2];
    const float* b_bil = (const float*)d_in[3];
    const float* w_out = (const float*)d_in[4];
    const float* b_out = (const float*)d_in[5];
    float* out = (float*)d_out;

    int ntok    = in_sizes[0] / 512;   // 32 channels * 16 components
    int ngroups = ntok / TPG;

    cudaFuncSetAttribute(gatr_fused_kernel,
                         cudaFuncAttributeMaxDynamicSharedMemorySize, SMEM_BYTES);
    gatr_fused_kernel<<<152, NTHR, SMEM_BYTES>>>(x, ref, w_bil, b_bil, w_out, b_out,
                                                 out, ngroups);
}

// round 17
// speedup vs baseline: 1.3122x; 1.0262x over previous
#include <cuda_runtime.h>

#define NTHR 512
#define TPG  16            // tokens per group

typedef unsigned long long ull;
typedef unsigned int uint;
typedef unsigned short ushort;

// ---------------- shared memory layout (uint indices) ----------------
// WB: [9][64][16] uint2 (hi,lo bf16-pair words), k2 XOR-permuted
// WO: [9][32][16] uint2
// XS: 16 rows x 264 uint2 (hi,lo) = x / gs staging, cols = slot*16 + token
// HS: fp32, 64 rows x 260
#define WB_OFF  0
#define WO_OFF  18432
#define XS_OFF  27648
#define HS_OFF  36096
#define BB_OFF  52736
#define BO_OFF  (BB_OFF + 64)
#define RW_OFF  (BO_OFF + 32)
#define F_TOTAL (RW_OFF + 16)
#define SMEM_BYTES (F_TOTAL * 4)   // 211392 B

__host__ __device__ constexpr int cslot(int k) { return k ^ (k >> 2); }

// ---------------- blade algebra ----------------
__constant__ int c_GRADE[16] = {0,1,1,1,1,2,2,2,2,2,2,3,3,3,3,4};
__constant__ int c_PART [16] = {-1,0,-1,-1,-1,2,3,4,-1,-1,-1,8,9,10,-1,14};
__constant__ int c_A2   [16] = {0,5,0,0,0,6,6,6,0,0,0,7,7,7,0,8};
__constant__ int c_KORD [16] = {1,5,6,7, 0,2,3,4, 11,12,13,15, 8,9,10,14};

constexpr int MASKC[16]  = {0,1,2,4,8,3,5,9,6,10,12,7,11,13,14,15};
constexpr int IMASKC[16] = {0,1,2,5,3,6,8,11,4,7,9,12,10,13,14,15};
constexpr int popc4c(int x) { int v = 0; for (int b = 0; b < 4; b++) v += (x >> b) & 1; return v; }
constexpr int invcc(int A, int B) {
    int v = 0;
    for (int g = 0; g < 4; g++) if ((B >> g) & 1) v += popc4c(A >> (g + 1));
    return v;
}
struct CTerm { int i, j, s; };
struct CK    { CTerm t[16]; int n; };
struct CTabs { CK gp[16]; CK jc[16]; };
constexpr CTabs buildT() {
    CTabs T{};
    for (int i = 0; i < 16; i++)
        for (int j = 0; j < 16; j++) {
            int A = MASKC[i], B = MASKC[j];
            if (A & B & 1) continue;
            int s = (invcc(A, B) & 1) ? -1 : 1;
            int k = IMASKC[A ^ B];
            T.gp[k].t[T.gp[k].n].i = i;
            T.gp[k].t[T.gp[k].n].j = j;
            T.gp[k].t[T.gp[k].n].s = s;
            T.gp[k].n++;
        }
    int ds[16] = {};
    for (int i = 0; i < 16; i++) {
        int A = MASKC[i];
        ds[i] = (invcc(A, 15 ^ A) & 1) ? -1 : 1;
    }
    for (int i = 0; i < 16; i++)
        for (int j = 0; j < 16; j++) {
            int A = MASKC[i], B = MASKC[j];
            int da = 15 ^ A, db = 15 ^ B;
            if (da & db) continue;
            int w  = (invcc(da, db) & 1) ? -1 : 1;
            int kk = IMASKC[A & B];
            int val = ds[i] * ds[j] * w * ds[kk];
            T.jc[kk].t[T.jc[kk].n].i = i;
            T.jc[kk].t[T.jc[kk].n].j = j;
            T.jc[kk].t[T.jc[kk].n].s = val;
            T.jc[kk].n++;
        }
    return T;
}
constexpr CTabs CT = buildT();

// ---- bf16 split helper: v = hi + lo (each bf16), error ~2^-17 ----
__device__ __forceinline__ void bsplit(float v, ushort& h, ushort& l) {
    asm("cvt.rn.bf16.f32 %0, %1;" : "=h"(h) : "f"(v));
    float hf = __uint_as_float(((uint)h) << 16);
    float r = v - hf;
    asm("cvt.rn.bf16.f32 %0, %1;" : "=h"(l) : "f"(r));
}

// ---- bf16 m16n8k16 mma ----
__device__ __forceinline__ void mma16(float (&c)[4],
                                      uint a0, uint a1, uint a2, uint a3,
                                      uint b0, uint b1) {
    asm volatile(
        "mma.sync.aligned.m16n8k16.row.col.f32.bf16.bf16.f32 "
        "{%0,%1,%2,%3}, {%4,%5,%6,%7}, {%8,%9}, {%0,%1,%2,%3};"
        : "+f"(c[0]), "+f"(c[1]), "+f"(c[2]), "+f"(c[3])
        : "r"(a0), "r"(a1), "r"(a2), "r"(a3), "r"(b0), "r"(b1));
}

// ---- one K=32 pass: C[MT][2][4] += W * X, 3-term bf16 split ----
// W: uint2 table [row][16] (kk permuted), X: uint2 [k2row*264 + col]
template<int MT>
__device__ __forceinline__ void bpass(
    float (&C)[MT][2][4], const uint2* __restrict__ W,
    const uint2* __restrict__ X, int sl, int p, int gr, int gc)
{
    #pragma unroll
    for (int s = 0; s < 2; s++) {
        int k0 = s * 8 + gc, k1 = k0 + 4;
        int i0 = k0 ^ p, i1 = k1 ^ p;
        uint2 B0[2], B1[2];
        #pragma unroll
        for (int nt = 0; nt < 2; nt++) {
            int bc = sl + nt * 8 + gr;
            B0[nt] = X[k0 * 264 + bc];
            B1[nt] = X[k1 * 264 + bc];
        }
        #pragma unroll
        for (int mt = 0; mt < MT; mt++) {
            int r0 = (mt * 16 + gr) * 16, r1 = r0 + 128;
            uint2 A0 = W[r0 + i0], A1 = W[r1 + i0];
            uint2 A2 = W[r0 + i1], A3 = W[r1 + i1];
            #pragma unroll
            for (int nt = 0; nt < 2; nt++) {
                mma16(C[mt][nt], A0.x, A1.x, A2.x, A3.x, B0[nt].x, B1[nt].x);
                mma16(C[mt][nt], A0.x, A1.x, A2.x, A3.x, B0[nt].y, B1[nt].y);
                mma16(C[mt][nt], A0.y, A1.y, A2.y, A3.y, B0[nt].x, B1[nt].x);
            }
        }
    }
}

// ---- P3 Cayley ----
template<int SIDE, int K>
__device__ __forceinline__ float bil_k(const float (&L)[16], const float (&R)[16]) {
    constexpr CK ck = SIDE ? CT.jc[K] : CT.gp[K];
    float acc = 0.f;
    #pragma unroll
    for (int e = 0; e < ck.n; e++) {
        float l = (ck.t[e].s < 0) ? -L[ck.t[e].i] : L[ck.t[e].i];
        acc = fmaf(l, R[ck.t[e].j], acc);
    }
    return acc;
}
template<int SIDE, int K>
__device__ __forceinline__ void bil_arr(const float (&L)[16], const float (&R)[16],
                                        float (&r)[16], float scale) {
    if constexpr (K < 16) {
        float v = bil_k<SIDE, K>(L, R);
        if constexpr (SIDE) v *= scale;
        r[K] = v;
        bil_arr<SIDE, K + 1>(L, R, r, scale);
    }
}

__global__ __launch_bounds__(NTHR, 1)
void gatr_fused_kernel(
    const float* __restrict__ x, const float* __restrict__ ref,
    const float* __restrict__ w_bil, const float* __restrict__ b_bil,
    const float* __restrict__ w_out, const float* __restrict__ b_out,
    float* __restrict__ out, int ngroups)
{
    extern __shared__ float smf[];
    uint*  smu = (uint*)smf;
    uint2* wbp = (uint2*)(smu + WB_OFF);
    uint2* wop = (uint2*)(smu + WO_OFF);
    uint2* xsp = (uint2*)(smu + XS_OFF);
    ushort* xsu = (ushort*)(smu + XS_OFF);
    float* bb = smf + BB_OFF;
    float* bo = smf + BO_OFF;
    float* rw = smf + RW_OFF;

    const int tid = threadIdx.x;

    // ---- stage weights: split to bf16 hi/lo pairs, k2-permuted ----
    for (int idx = tid; idx < 9216; idx += NTHR) {      // 9*64*16
        int k2 = idx & 15, o = (idx >> 4) & 63, a = idx >> 10;
        float v0 = w_bil[o * 288 + (2 * k2) * 9 + a];
        float v1 = w_bil[o * 288 + (2 * k2 + 1) * 9 + a];
        ushort h0, l0, h1, l1;
        bsplit(v0, h0, l0); bsplit(v1, h1, l1);
        int kk = k2 ^ (((o >> 1) & 3) << 2);
        wbp[a * 1024 + o * 16 + kk] =
            make_uint2((uint)h0 | ((uint)h1 << 16), (uint)l0 | ((uint)l1 << 16));
    }
    for (int idx = tid; idx < 4608; idx += NTHR) {      // 9*32*16
        int k2 = idx & 15, o = (idx >> 4) & 31, a = idx >> 9;
        float v0 = w_out[o * 288 + (2 * k2) * 9 + a];
        float v1 = w_out[o * 288 + (2 * k2 + 1) * 9 + a];
        ushort h0, l0, h1, l1;
        bsplit(v0, h0, l0); bsplit(v1, h1, l1);
        int kk = k2 ^ (((o >> 1) & 3) << 2);
        wop[a * 512 + o * 16 + kk] =
            make_uint2((uint)h0 | ((uint)h1 << 16), (uint)l0 | ((uint)l1 << 16));
    }
    if (tid < 64) bb[tid] = b_bil[tid];
    if (tid < 32) bo[tid] = b_out[tid];

    const int e_id = tid & 127;
    const int t0   = (tid >> 7) * 4;
    const int i_my = e_id >> 2, half = i_my & 1;
    const int rb   = (i_my >> 1) * 264;

    // ---- prefetch + stage first group (split bf16 staging) ----
    float4 pf[4];
    float  prw = 0.f;
    {
        int g = blockIdx.x;
        size_t base = ((size_t)g * TPG + t0) * 512 + (size_t)e_id * 4;
        #pragma unroll
        for (int j = 0; j < 4; j++) pf[j] = *(const float4*)(x + base + (size_t)j * 512);
        if (tid < TPG) prw = ref[((size_t)g * TPG + tid) * 16 + 15];

        #pragma unroll
        for (int c = 0; c < 4; c++) {
            int k = (e_id & 3) * 4 + c;
            int cb = cslot(k) * 16 + t0;
            #pragma unroll
            for (int j = 0; j < 4; j++) {
                float v = ((const float*)&pf[j])[c];
                ushort h, l; bsplit(v, h, l);
                int w4 = (rb + cb + j) * 4;
                xsu[w4 + half] = h;
                xsu[w4 + 2 + half] = l;
            }
        }
        if (tid < TPG) rw[tid] = prw;
    }

    const int w_id = tid >> 5, lane = tid & 31;
    const int gr = lane >> 2, gc = lane & 3;
    const int pperm = ((gr >> 1) & 3) << 2;
    const int k_my  = c_KORD[w_id];
    const int pk_my = c_PART[k_my];
    const int sl_my = cslot(k_my) * 16;

    for (int g = blockIdx.x; g < ngroups; g += gridDim.x) {
        __syncthreads();   // xs / rw / weights ready

        // ---- P2: equi_linear #1 via bf16 mma -> hs rows 0..63 ----
        {
            float C[4][2][4];
            #pragma unroll
            for (int mt = 0; mt < 4; mt++)
                #pragma unroll
                for (int nt = 0; nt < 2; nt++)
                    #pragma unroll
                    for (int j = 0; j < 4; j++) C[mt][nt][j] = 0.f;

            bpass<4>(C, wbp + c_GRADE[k_my] * 1024, xsp, sl_my, pperm, gr, gc);
            if (pk_my >= 0)
                bpass<4>(C, wbp + c_A2[k_my] * 1024, xsp, cslot(pk_my) * 16,
                         pperm, gr, gc);

            if (k_my == 0) {
                #pragma unroll
                for (int mt = 0; mt < 4; mt++) {
                    float bA = bb[mt * 16 + gr], bB = bb[mt * 16 + gr + 8];
                    #pragma unroll
                    for (int nt = 0; nt < 2; nt++) {
                        C[mt][nt][0] += bA; C[mt][nt][1] += bA;
                        C[mt][nt][2] += bB; C[mt][nt][3] += bB;
                    }
                }
            }
            #pragma unroll
            for (int mt = 0; mt < 4; mt++) {
                int o = mt * 16 + gr;
                #pragma unroll
                for (int nt = 0; nt < 2; nt++) {
                    int col = sl_my + nt * 8 + 2 * gc;
                    *(float2*)(smf + HS_OFF + o * 260 + col) =
                        make_float2(C[mt][nt][0], C[mt][nt][1]);
                    *(float2*)(smf + HS_OFF + (o + 8) * 260 + col) =
                        make_float2(C[mt][nt][2], C[mt][nt][3]);
                }
            }
        }
        __syncthreads();

        // ---- P3: GP + join -> gs (xs region, split bf16) ----
        {
            int side = tid >> 8, c = (tid >> 4) & 15, t = tid & 15;
            const float* Lp = smf + HS_OFF + (side * 32 + c) * 260 + t;
            const float* Rp = smf + HS_OFF + (side * 32 + 16 + c) * 260 + t;
            float L[16], R[16];
            #pragma unroll
            for (int i = 0; i < 16; i++) {
                L[i] = Lp[cslot(i) * 16];
                R[i] = Rp[cslot(i) * 16];
            }
            float r[16];
            float scale = rw[t];
            if (side == 0) bil_arr<0, 0>(L, R, r, scale);
            else           bil_arr<1, 0>(L, R, r, scale);

            int rowc = side * 8 + (c >> 1);
            int hl = c & 1;
            #pragma unroll
            for (int K = 0; K < 16; K++) {
                ushort h, l; bsplit(r[K], h, l);
                int w4 = (rowc * 264 + cslot(K) * 16 + t) * 4;
                xsu[w4 + hl] = h;
                xsu[w4 + 2 + hl] = l;
            }
        }
        __syncthreads();

        // prefetch next group (latency covered by P4)
        int gn = g + gridDim.x;
        bool more = gn < ngroups;
        if (more) {
            size_t base = ((size_t)gn * TPG + t0) * 512 + (size_t)e_id * 4;
            #pragma unroll
            for (int j = 0; j < 4; j++) pf[j] = *(const float4*)(x + base + (size_t)j * 512);
            if (tid < TPG) prw = ref[((size_t)gn * TPG + tid) * 16 + 15];
        }

        // ---- P4: equi_linear #2 via bf16 mma -> hs rows 0..31 ----
        {
            float C[2][2][4];
            #pragma unroll
            for (int mt = 0; mt < 2; mt++)
                #pragma unroll
                for (int nt = 0; nt < 2; nt++)
                    #pragma unroll
                    for (int j = 0; j < 4; j++) C[mt][nt][j] = 0.f;

            bpass<2>(C, wop + c_GRADE[k_my] * 512, xsp, sl_my, pperm, gr, gc);
            if (pk_my >= 0)
                bpass<2>(C, wop + c_A2[k_my] * 512, xsp, cslot(pk_my) * 16,
                         pperm, gr, gc);

            if (k_my == 0) {
                #pragma unroll
                for (int mt = 0; mt < 2; mt++) {
                    float bA = bo[mt * 16 + gr], bB = bo[mt * 16 + gr + 8];
                    #pragma unroll
                    for (int nt = 0; nt < 2; nt++) {
                        C[mt][nt][0] += bA; C[mt][nt][1] += bA;
                        C[mt][nt][2] += bB; C[mt][nt][3] += bB;
                    }
                }
            }
            #pragma unroll
            for (int mt = 0; mt < 2; mt++) {
                int o = mt * 16 + gr;
                #pragma unroll
                for (int nt = 0; nt < 2; nt++) {
                    int col = sl_my + nt * 8 + 2 * gc;
                    *(float2*)(smf + HS_OFF + o * 260 + col) =
                        make_float2(C[mt][nt][0], C[mt][nt][1]);
                    *(float2*)(smf + HS_OFF + (o + 8) * 260 + col) =
                        make_float2(C[mt][nt][2], C[mt][nt][3]);
                }
            }
        }
        __syncthreads();

        // ---- P5: coalesced store + stage next group's x ----
        {
            float4 sv[4];
            #pragma unroll
            for (int c = 0; c < 4; c++) {
                int k = (e_id & 3) * 4 + c;
                sv[c] = *(const float4*)(smf + HS_OFF + (e_id >> 2) * 260 +
                                         cslot(k) * 16 + t0);
            }
            size_t base = ((size_t)g * TPG + t0) * 512 + (size_t)e_id * 4;
            const float* s0 = (const float*)&sv[0];
            const float* s1 = (const float*)&sv[1];
            const float* s2 = (const float*)&sv[2];
            const float* s3 = (const float*)&sv[3];
            #pragma unroll
            for (int j = 0; j < 4; j++)
                *(float4*)(out + base + (size_t)j * 512) =
                    make_float4(s0[j], s1[j], s2[j], s3[j]);

            if (more) {
                #pragma unroll
                for (int c = 0; c < 4; c++) {
                    int k = (e_id & 3) * 4 + c;
                    int cb = cslot(k) * 16 + t0;
                    #pragma unroll
                    for (int j = 0; j < 4; j++) {
                        float v = ((const float*)&pf[j])[c];
                        ushort h, l; bsplit(v, h, l);
                        int w4 = (rb + cb + j) * 4;
                        xsu[w4 + half] = h;
                        xsu[w4 + 2 + half] = l;
                    }
                }
                if (tid < TPG) rw[tid] = prw;
            }
        }
    }
}

extern "C" void kernel_launch(void* const* d_in, const int* in_sizes, int n_in,
                              void* d_out, int out_size)
{
    const float* x     = (const float*)d_in[0];
    const float* ref   = (const float*)d_in[1];
    const float* w_bil = (const float*)d_in[2];
    const float* b_bil = (const float*)d_in[3];
    const float* w_out = (const float*)d_in[4];
    const float* b_out = (const float*)d_in[5];
    float* out = (float*)d_out;

    int ntok    = in_sizes[0] / 512;
    int ngroups = ntok / TPG;

    cudaFuncSetAttribute(gatr_fused_kernel,
                         cudaFuncAttributeMaxDynamicSharedMemorySize, SMEM_BYTES);
    gatr_fused_kernel<<<152, NTHR, SMEM_BYTES>>>(x, ref, w_bil, b_bil, w_out, b_out,
                                                 out, ngroups);
}